// round 9
// baseline (speedup 1.0000x reference)
#include <cuda_runtime.h>
#include <cuda_bf16.h>
#include <cstdint>

#define DIM    128
#define BATCH  1048576
#define NTILES (BATCH / DIM)   // 8192
#define GRID   152
#define PITCHB 272             // bf16 smem row pitch (17 x 16B -> LDSM conflict-free)

// ---------------------------------------------------------------------------
// helpers
// ---------------------------------------------------------------------------
__device__ __forceinline__ uint32_t smem_u32(const void* p) {
    uint32_t a;
    asm("{ .reg .u64 t; cvta.to.shared.u64 t, %1; cvt.u32.u64 %0, t; }"
        : "=r"(a) : "l"(p));
    return a;
}

__device__ __forceinline__ unsigned short bfbits(__nv_bfloat16 h) {
    return *reinterpret_cast<unsigned short*>(&h);
}

#define MMA16816(d, a, b)                                                        \
    asm volatile(                                                                \
        "mma.sync.aligned.m16n8k16.row.col.f32.bf16.bf16.f32 "                   \
        "{%0,%1,%2,%3}, {%4,%5,%6,%7}, {%8,%9}, {%0,%1,%2,%3};"                  \
        : "+f"((d)[0]), "+f"((d)[1]), "+f"((d)[2]), "+f"((d)[3])                 \
        : "r"((a)[0]), "r"((a)[1]), "r"((a)[2]), "r"((a)[3]),                    \
          "r"((b)[0]), "r"((b)[1]))

#define LDSM4(r, addr)                                                           \
    asm volatile("ldmatrix.sync.aligned.m8n8.x4.shared.b16 {%0,%1,%2,%3}, [%4];" \
                 : "=r"((r)[0]), "=r"((r)[1]), "=r"((r)[2]), "=r"((r)[3])        \
                 : "r"(addr))

#define LDSM2(r, addr)                                                           \
    asm volatile("ldmatrix.sync.aligned.m8n8.x2.shared.b16 {%0,%1}, [%2];"       \
                 : "=r"((r)[0]), "=r"((r)[1])                                    \
                 : "r"(addr))

#define CP_ASYNC16(smem_addr, gptr)                                              \
    asm volatile("cp.async.cg.shared.global [%0], [%1], 16;"                     \
                 :: "r"(smem_addr), "l"(gptr))
#define CP_COMMIT() asm volatile("cp.async.commit_group;")
#define CP_WAIT0()  asm volatile("cp.async.wait_group 0;")

// ---------------------------------------------------------------------------
// Global scratch: W = Q*diag*s split into bf16 hi/lo, row-major W_B[n][k]
// (i.e. element [n*DIM+k] = W[k][n], the col-major B operand)
// ---------------------------------------------------------------------------
__device__ __align__(16) __nv_bfloat16 g_Whi[DIM * DIM];
__device__ __align__(16) __nv_bfloat16 g_Wlo[DIM * DIM];

// ---------------------------------------------------------------------------
// Kernel 1: build Q via 128 sequential Householder reflections.
// Q's rows evolve independently: q_r <- q_r - 2 (q_r . vhat) vhat^T.
// So split the 128 rows across 8 CTAs (16 rows each, 4 threads/row,
// 32 floats per thread). Each CTA redundantly loads V (transposed into
// smem) and pre-normalizes all 128 vhat columns, then runs the sequential
// loop sync-free (dot combined with 2 shfls within the 4-lane row group).
// ---------------------------------------------------------------------------
#define VPITCH 132
#define BW_SMEM (DIM * VPITCH * 4)   // 67584
#define BW_THREADS 64

__global__ void __launch_bounds__(BW_THREADS, 1)
build_w_kernel(const float* __restrict__ V, const float* __restrict__ scale,
               const float* __restrict__ diag, float* __restrict__ out,
               int out_size) {
    extern __shared__ float sv[];        // sv[col * VPITCH + row] = vhat
    __shared__ float s_invn[DIM];

    int t   = threadIdx.x;               // 0..63
    int row = blockIdx.x * 16 + (t >> 2);  // this thread's Q row
    int sub = t & 3;                     // 32-float segment of the row

    // ---- load V transposed into smem ----
#pragma unroll 4
    for (int it = 0; it < 256; it++) {
        int idx = it * BW_THREADS + t;        // 0..16383
        int r0 = idx >> 7, c0 = idx & 127;    // V[r0][c0], columns are v_i
        sv[c0 * VPITCH + r0] = V[idx];
    }
    __syncthreads();

    // ---- 1/(||v_i|| + eps), 2 columns per thread ----
#pragma unroll
    for (int cc = 0; cc < 2; cc++) {
        int col = cc * BW_THREADS + t;
        float ss = 0.0f;
        const float* c = sv + col * VPITCH;
#pragma unroll 8
        for (int j = 0; j < DIM; j++) ss += c[j] * c[j];
        s_invn[col] = 1.0f / (sqrtf(ss) + 1e-8f);
    }
    __syncthreads();

    // ---- normalize columns in place ----
#pragma unroll 4
    for (int it = 0; it < 256; it++) {
        int idx = it * BW_THREADS + t;
        int r0 = idx & 127, c0 = idx >> 7;
        sv[c0 * VPITCH + r0] *= s_invn[c0];
    }
    __syncthreads();

    // ---- this thread's 32 floats of its Q row, identity init ----
    float q[32];
#pragma unroll
    for (int j = 0; j < 32; j++) q[j] = 0.0f;
    {
        int c0 = sub * 32;
        if (row >= c0 && row < c0 + 32) q[row - c0] = 1.0f;
    }

    // ---- sequential reflections ----
    for (int i = 0; i < DIM; i++) {
        const float4* vb = (const float4*)(sv + i * VPITCH + sub * 32);
        float4 v4[8];
#pragma unroll
        for (int j4 = 0; j4 < 8; j4++) v4[j4] = vb[j4];

        float d0 = 0.f, d1 = 0.f, d2 = 0.f, d3 = 0.f;
#pragma unroll
        for (int j4 = 0; j4 < 8; j4++) {
            d0 += q[4 * j4 + 0] * v4[j4].x;
            d1 += q[4 * j4 + 1] * v4[j4].y;
            d2 += q[4 * j4 + 2] * v4[j4].z;
            d3 += q[4 * j4 + 3] * v4[j4].w;
        }
        float dp = (d0 + d1) + (d2 + d3);
        dp += __shfl_xor_sync(0xffffffffu, dp, 1);
        dp += __shfl_xor_sync(0xffffffffu, dp, 2);   // full row dot
        float coef = 2.0f * dp;
#pragma unroll
        for (int j4 = 0; j4 < 8; j4++) {
            q[4 * j4 + 0] -= coef * v4[j4].x;
            q[4 * j4 + 1] -= coef * v4[j4].y;
            q[4 * j4 + 2] -= coef * v4[j4].z;
            q[4 * j4 + 3] -= coef * v4[j4].w;
        }
    }

    // ---- W[row][c] = Q[row][c]*diag[c]*s, stored as W_B[c][row], bf16 hi+lo
    float s = scale[0];
#pragma unroll
    for (int j = 0; j < 32; j++) {
        int c = sub * 32 + j;
        float w = q[j] * diag[c] * s;
        __nv_bfloat16 hi = __float2bfloat16(w);
        float lof = w - __bfloat162float(hi);
        g_Whi[c * DIM + row] = hi;
        g_Wlo[c * DIM + row] = __float2bfloat16(lof);
    }

    if (blockIdx.x == 0 && t == 0 && out_size > BATCH * DIM) {
        float ld = 0.0f;
        for (int c = 0; c < DIM; c++) ld += logf(fabsf(diag[c] * s) + 1e-8f);
        out[(size_t)BATCH * DIM] = ld;
    }
}

// ---------------------------------------------------------------------------
// Kernel 2: y = x @ W, mma.sync bf16 split (hi*hi + hi*lo + lo*hi).
// Persistent 152 CTAs x 256 thr (8 warps). 2-D warp tiling: each warp owns a
// 64M x 32N output block (2x4 warp grid) -> A LDSM traffic 32KB/warp and
// B (W) LDSM 16KB/warp per tile (384KB total vs 512KB for 1-D N tiling).
// W lives in smem (loaded once); x staged via cp.async into raw fp32 smem,
// converted to bf16 hi/lo per tile. 16 independent accumulator frags per
// warp; MMAs issued in 3 product passes for max reuse distance.
// ---------------------------------------------------------------------------
#define SM_RAW 0                          // 65536
#define SM_XHI 65536                      // 34816
#define SM_XLO (65536 + 34816)            // 34816
#define SM_WHI (65536 + 2 * 34816)        // 34816
#define SM_WLO (65536 + 3 * 34816)        // 34816
#define SMEM_BYTES (65536 + 4 * 34816)    // 204800

__global__ void __launch_bounds__(256, 1)
gemm_kernel(const float* __restrict__ x, float* __restrict__ y) {
    extern __shared__ char sm[];
    float* smRaw = (float*)(sm + SM_RAW);
    uint32_t sbXhi = smem_u32(sm + SM_XHI);
    uint32_t sbXlo = smem_u32(sm + SM_XLO);
    uint32_t sbWhi = smem_u32(sm + SM_WHI);
    uint32_t sbWlo = smem_u32(sm + SM_WLO);

    int t = threadIdx.x, wid = t >> 5, lane = t & 31;
    int g = lane >> 2, tid4 = lane & 3;
    int mrow = (wid & 1) * 64;            // warp-tile M origin
    int ncol = (wid >> 1) * 32;           // warp-tile N origin

    // A ldmatrix lane addressing
    uint32_t lrow = (uint32_t)(lane & 15);
    uint32_t lcol = (uint32_t)((lane >> 4) << 3);
    // B ldmatrix.x2 lane addressing (lanes 0-15 used)
    uint32_t brow = (uint32_t)(lane & 7);
    uint32_t bk   = (uint32_t)(((lane >> 3) & 1) << 3);

    int tile = blockIdx.x;
    if (tile >= NTILES) return;

    // ---- prologue: stage tile 0 raw ----
    {
        const float4* src = (const float4*)(x + (size_t)tile * DIM * DIM);
#pragma unroll
        for (int it = 0; it < 16; it++) {
            int idx = it * 256 + t;               // 4096 x 16B chunks
            CP_ASYNC16(smem_u32(smRaw) + idx * 16, src + idx);
        }
        CP_COMMIT();
    }

    // ---- load W hi/lo into pitched smem (once) ----
#pragma unroll
    for (int it = 0; it < 8; it++) {
        int idx = it * 256 + t;               // 2048 x 16B chunks
        int n = idx >> 4, c16 = idx & 15;     // row n, 16B chunk
        *(uint4*)(sm + SM_WHI + n * PITCHB + c16 * 16) =
            *(const uint4*)((const char*)g_Whi + idx * 16);
        *(uint4*)(sm + SM_WLO + n * PITCHB + c16 * 16) =
            *(const uint4*)((const char*)g_Wlo + idx * 16);
    }

    while (true) {
        CP_WAIT0();
        __syncthreads();   // raw ready AND prev tile's readers done

        // ---- convert raw fp32 -> bf16 hi/lo smem ----
#pragma unroll
        for (int it = 0; it < 16; it++) {
            int idx = it * 256 + t;
            int row = idx >> 5, c5 = idx & 31;
            float4 v = *(const float4*)(smRaw + (size_t)idx * 4);
            __nv_bfloat16 h0 = __float2bfloat16(v.x);
            __nv_bfloat16 h1 = __float2bfloat16(v.y);
            __nv_bfloat16 h2 = __float2bfloat16(v.z);
            __nv_bfloat16 h3 = __float2bfloat16(v.w);
            __nv_bfloat16 l0 = __float2bfloat16(v.x - __bfloat162float(h0));
            __nv_bfloat16 l1 = __float2bfloat16(v.y - __bfloat162float(h1));
            __nv_bfloat16 l2 = __float2bfloat16(v.z - __bfloat162float(h2));
            __nv_bfloat16 l3 = __float2bfloat16(v.w - __bfloat162float(h3));
            uint2 hv, lv;
            hv.x = (uint32_t)bfbits(h0) | ((uint32_t)bfbits(h1) << 16);
            hv.y = (uint32_t)bfbits(h2) | ((uint32_t)bfbits(h3) << 16);
            lv.x = (uint32_t)bfbits(l0) | ((uint32_t)bfbits(l1) << 16);
            lv.y = (uint32_t)bfbits(l2) | ((uint32_t)bfbits(l3) << 16);
            *(uint2*)(sm + SM_XHI + row * PITCHB + c5 * 8) = hv;
            *(uint2*)(sm + SM_XLO + row * PITCHB + c5 * 8) = lv;
        }
        __syncthreads();   // hi/lo ready; raw fully consumed

        // ---- stage next tile while computing ----
        int next = tile + GRID;
        if (next < NTILES) {
            const float4* src = (const float4*)(x + (size_t)next * DIM * DIM);
#pragma unroll
            for (int it = 0; it < 16; it++) {
                int idx = it * 256 + t;
                CP_ASYNC16(smem_u32(smRaw) + idx * 16, src + idx);
            }
            CP_COMMIT();
        }

        // ---- compute: 64M x 32N warp tile ----
        float acc[4][4][4];
#pragma unroll
        for (int i = 0; i < 4; i++)
#pragma unroll
            for (int j = 0; j < 4; j++)
#pragma unroll
                for (int e = 0; e < 4; e++) acc[i][j][e] = 0.0f;

#pragma unroll
        for (int ks = 0; ks < 8; ks++) {
            uint32_t Ah[4][4], Al[4][4];
#pragma unroll
            for (int i = 0; i < 4; i++) {
                uint32_t off = (uint32_t)(mrow + i * 16 + lrow) * PITCHB +
                               (uint32_t)(ks * 16 + lcol) * 2;
                LDSM4(Ah[i], sbXhi + off);
                LDSM4(Al[i], sbXlo + off);
            }
            uint32_t Bh[4][2], Bl[4][2];
#pragma unroll
            for (int j = 0; j < 4; j++) {
                uint32_t boff = (uint32_t)(ncol + j * 8 + brow) * PITCHB +
                                (uint32_t)(ks * 16 + bk) * 2;
                LDSM2(Bh[j], sbWhi + boff);
                LDSM2(Bl[j], sbWlo + boff);
            }
            // pass 1: hi*hi
#pragma unroll
            for (int i = 0; i < 4; i++)
#pragma unroll
                for (int j = 0; j < 4; j++) MMA16816(acc[i][j], Ah[i], Bh[j]);
            // pass 2: hi*lo
#pragma unroll
            for (int i = 0; i < 4; i++)
#pragma unroll
                for (int j = 0; j < 4; j++) MMA16816(acc[i][j], Ah[i], Bl[j]);
            // pass 3: lo*hi
#pragma unroll
            for (int i = 0; i < 4; i++)
#pragma unroll
                for (int j = 0; j < 4; j++) MMA16816(acc[i][j], Al[i], Bh[j]);
        }

        // ---- store ----
        float* yt = y + (size_t)tile * DIM * DIM;
#pragma unroll
        for (int i = 0; i < 4; i++) {
            int row0 = mrow + i * 16 + g;
#pragma unroll
            for (int j = 0; j < 4; j++) {
                int cb = ncol + j * 8 + tid4 * 2;
                float2 v0, v1;
                v0.x = acc[i][j][0]; v0.y = acc[i][j][1];
                v1.x = acc[i][j][2]; v1.y = acc[i][j][3];
                __stcs((float2*)(yt + (size_t)row0 * DIM + cb), v0);
                __stcs((float2*)(yt + (size_t)(row0 + 8) * DIM + cb), v1);
            }
        }

        tile = next;
        if (tile >= NTILES) break;
    }
}

// ---------------------------------------------------------------------------
// Launch
// ---------------------------------------------------------------------------
extern "C" void kernel_launch(void* const* d_in, const int* in_sizes, int n_in,
                              void* d_out, int out_size) {
    const float* x    = (const float*)d_in[0];   // [BATCH, DIM]
    const float* V    = (const float*)d_in[1];   // [DIM, DIM] (v_i = columns)
    const float* sc   = (const float*)d_in[2];   // [1]
    const float* diag = (const float*)d_in[3];   // [DIM]
    float* out = (float*)d_out;

    cudaFuncSetAttribute(build_w_kernel,
                         cudaFuncAttributeMaxDynamicSharedMemorySize, BW_SMEM);
    cudaFuncSetAttribute(gemm_kernel,
                         cudaFuncAttributeMaxDynamicSharedMemorySize, SMEM_BYTES);

    build_w_kernel<<<8, BW_THREADS, BW_SMEM>>>(V, sc, diag, out, out_size);
    gemm_kernel<<<GRID, 256, SMEM_BYTES>>>(x, out);
}

// round 10
// speedup vs baseline: 1.1071x; 1.1071x over previous
#include <cuda_runtime.h>
#include <cuda_bf16.h>
#include <cstdint>

#define DIM    128
#define BATCH  1048576
#define NTILES (BATCH / DIM)   // 8192
#define GRID   152
#define PITCHB 272             // bf16 smem row pitch (17 x 16B -> LDSM conflict-free)

// ---------------------------------------------------------------------------
// helpers
// ---------------------------------------------------------------------------
__device__ __forceinline__ uint32_t smem_u32(const void* p) {
    uint32_t a;
    asm("{ .reg .u64 t; cvta.to.shared.u64 t, %1; cvt.u32.u64 %0, t; }"
        : "=r"(a) : "l"(p));
    return a;
}

__device__ __forceinline__ unsigned short bfbits(__nv_bfloat16 h) {
    return *reinterpret_cast<unsigned short*>(&h);
}

#define MMA16816(d, a, b)                                                        \
    asm volatile(                                                                \
        "mma.sync.aligned.m16n8k16.row.col.f32.bf16.bf16.f32 "                   \
        "{%0,%1,%2,%3}, {%4,%5,%6,%7}, {%8,%9}, {%0,%1,%2,%3};"                  \
        : "+f"((d)[0]), "+f"((d)[1]), "+f"((d)[2]), "+f"((d)[3])                 \
        : "r"((a)[0]), "r"((a)[1]), "r"((a)[2]), "r"((a)[3]),                    \
          "r"((b)[0]), "r"((b)[1]))

#define LDSM4(r, addr)                                                           \
    asm volatile("ldmatrix.sync.aligned.m8n8.x4.shared.b16 {%0,%1,%2,%3}, [%4];" \
                 : "=r"((r)[0]), "=r"((r)[1]), "=r"((r)[2]), "=r"((r)[3])        \
                 : "r"(addr))

#define LDSM2(r, addr)                                                           \
    asm volatile("ldmatrix.sync.aligned.m8n8.x2.shared.b16 {%0,%1}, [%2];"       \
                 : "=r"((r)[0]), "=r"((r)[1])                                    \
                 : "r"(addr))

// named producer/consumer barriers (count = all 384 threads)
#define BAR_SYNC(id)   asm volatile("bar.sync %0, 384;"   :: "r"(id) : "memory")
#define BAR_ARRIVE(id) asm volatile("bar.arrive %0, 384;" :: "r"(id) : "memory")

// ---------------------------------------------------------------------------
// Global scratch: W_B[n][k] = W[k][n]*... split into bf16 hi/lo
// ---------------------------------------------------------------------------
__device__ __align__(16) __nv_bfloat16 g_Whi[DIM * DIM];
__device__ __align__(16) __nv_bfloat16 g_Wlo[DIM * DIM];

// ---------------------------------------------------------------------------
// Kernel 1: build Q via 128 sequential Householder reflections.
// 4 CTAs x 256 threads; each CTA owns 32 Q rows (8 threads/row, 16 floats
// per thread). Each CTA redundantly loads V transposed into smem and
// pre-normalizes the 128 vhat columns; the sequential loop is sync-free
// (row dot combined with 3 shfls inside the 8-lane row group).
// ---------------------------------------------------------------------------
#define VPITCH 132
#define BW_SMEM (DIM * VPITCH * 4)   // 67584

__global__ void __launch_bounds__(256, 1)
build_w_kernel(const float* __restrict__ V, const float* __restrict__ scale,
               const float* __restrict__ diag, float* __restrict__ out,
               int out_size) {
    extern __shared__ float sv[];        // sv[col * VPITCH + row] = vhat
    __shared__ float s_invn[DIM];

    int t   = threadIdx.x;               // 0..255
    int row = blockIdx.x * 32 + (t >> 3);  // this thread's Q row
    int sub = t & 7;                     // 16-float segment of the row

    // ---- load V transposed into smem (coalesced) ----
#pragma unroll
    for (int it = 0; it < 64; it++) {
        int idx = it * 256 + t;               // 0..16383
        int r0 = idx >> 7, c0 = idx & 127;    // V[r0][c0], columns are v_i
        sv[c0 * VPITCH + r0] = V[idx];
    }
    __syncthreads();

    // ---- 1/(||v_i|| + eps) ----
    if (t < DIM) {
        float ss = 0.0f;
        const float* c = sv + t * VPITCH;
#pragma unroll 8
        for (int j = 0; j < DIM; j++) ss += c[j] * c[j];
        s_invn[t] = 1.0f / (sqrtf(ss) + 1e-8f);
    }
    __syncthreads();

    // ---- normalize columns in place ----
#pragma unroll
    for (int it = 0; it < 64; it++) {
        int idx = it * 256 + t;
        int r0 = idx & 127, c0 = idx >> 7;
        sv[c0 * VPITCH + r0] *= s_invn[c0];
    }
    __syncthreads();

    // ---- this thread's 16 floats of its Q row, identity init ----
    float q[16];
#pragma unroll
    for (int j = 0; j < 16; j++) q[j] = 0.0f;
    {
        int c0 = sub * 16;
        if (row >= c0 && row < c0 + 16) q[row - c0] = 1.0f;
    }

    // ---- sequential reflections ----
    for (int i = 0; i < DIM; i++) {
        const float4* vb = (const float4*)(sv + i * VPITCH + sub * 16);
        float4 v4[4];
#pragma unroll
        for (int j4 = 0; j4 < 4; j4++) v4[j4] = vb[j4];

        float d0 = 0.f, d1 = 0.f, d2 = 0.f, d3 = 0.f;
#pragma unroll
        for (int j4 = 0; j4 < 4; j4++) {
            d0 += q[4 * j4 + 0] * v4[j4].x;
            d1 += q[4 * j4 + 1] * v4[j4].y;
            d2 += q[4 * j4 + 2] * v4[j4].z;
            d3 += q[4 * j4 + 3] * v4[j4].w;
        }
        float dp = (d0 + d1) + (d2 + d3);
        dp += __shfl_xor_sync(0xffffffffu, dp, 1);
        dp += __shfl_xor_sync(0xffffffffu, dp, 2);
        dp += __shfl_xor_sync(0xffffffffu, dp, 4);   // full row dot (8 lanes)
        float coef = 2.0f * dp;
#pragma unroll
        for (int j4 = 0; j4 < 4; j4++) {
            q[4 * j4 + 0] -= coef * v4[j4].x;
            q[4 * j4 + 1] -= coef * v4[j4].y;
            q[4 * j4 + 2] -= coef * v4[j4].z;
            q[4 * j4 + 3] -= coef * v4[j4].w;
        }
    }

    // ---- W[row][c] = Q[row][c]*diag[c]*s, stored as W_B[c][row], bf16 hi+lo
    float s = scale[0];
#pragma unroll
    for (int j = 0; j < 16; j++) {
        int c = sub * 16 + j;
        float w = q[j] * diag[c] * s;
        __nv_bfloat16 hi = __float2bfloat16(w);
        float lof = w - __bfloat162float(hi);
        g_Whi[c * DIM + row] = hi;
        g_Wlo[c * DIM + row] = __float2bfloat16(lof);
    }

    if (blockIdx.x == 0 && t == 0 && out_size > BATCH * DIM) {
        float ld = 0.0f;
        for (int c = 0; c < DIM; c++) ld += logf(fabsf(diag[c] * s) + 1e-8f);
        out[(size_t)BATCH * DIM] = ld;
    }
}

// ---------------------------------------------------------------------------
// Kernel 2: y = x @ W, warp-specialized producer/consumer pipeline.
// 384 threads: warps 0-7 consumers (64M x 32N warp tiles, 3-product bf16
// split MMA), warps 8-11 producers (LDG fp32 -> split bf16 hi/lo -> STS).
// Double-buffered X hi/lo smem; named-barrier ping-pong so the tensor pipe
// never waits on convert. W hi/lo in smem, loaded once.
// ---------------------------------------------------------------------------
#define SM_XHI0 0
#define SM_XLO0 34816
#define SM_XHI1 69632
#define SM_XLO1 104448
#define SM_WHI  139264
#define SM_WLO  174080
#define SMEM_BYTES 208896

// barrier ids: full[b] = 1+b (prod arrive, cons sync)
//              empty[b] = 3+b (cons arrive, prod sync)

__global__ void __launch_bounds__(384, 1)
gemm_kernel(const float* __restrict__ x, float* __restrict__ y) {
    extern __shared__ char sm[];
    uint32_t sb = smem_u32(sm);
    uint32_t sbXhi[2] = {sb + SM_XHI0, sb + SM_XHI1};
    uint32_t sbXlo[2] = {sb + SM_XLO0, sb + SM_XLO1};
    uint32_t sbWhi = sb + SM_WHI;
    uint32_t sbWlo = sb + SM_WLO;

    int t = threadIdx.x, wid = t >> 5, lane = t & 31;

    // ---- load W hi/lo into pitched smem (once, all threads) ----
    for (int idx = t; idx < 2048; idx += 384) {        // 16B chunks
        int n = idx >> 4, c16 = idx & 15;
        *(uint4*)(sm + SM_WHI + n * PITCHB + c16 * 16) =
            *(const uint4*)((const char*)g_Whi + idx * 16);
        *(uint4*)(sm + SM_WLO + n * PITCHB + c16 * 16) =
            *(const uint4*)((const char*)g_Wlo + idx * 16);
    }
    __syncthreads();

    if (wid >= 8) {
        // ================= PRODUCER (warps 8-11, 128 threads) =================
        int pt = t - 256;                 // 0..127
        int i = 0;
        for (int tile = blockIdx.x; tile < NTILES; tile += GRID, i++) {
            int b = i & 1;
            const float4* src = (const float4*)(x + (size_t)tile * DIM * DIM);
            float4 f[32];
#pragma unroll
            for (int c = 0; c < 32; c++) f[c] = __ldcs(src + c * 128 + pt);

            if (i >= 2) BAR_SYNC(3 + b);           // wait empty[b]

            char* dsthi = sm + (b ? SM_XHI1 : SM_XHI0);
            char* dstlo = sm + (b ? SM_XLO1 : SM_XLO0);
#pragma unroll
            for (int c = 0; c < 32; c++) {
                int idx = c * 128 + pt;            // float4 chunk id
                int row = idx >> 5, c5 = idx & 31;
                float4 v = f[c];
                __nv_bfloat16 h0 = __float2bfloat16(v.x);
                __nv_bfloat16 h1 = __float2bfloat16(v.y);
                __nv_bfloat16 h2 = __float2bfloat16(v.z);
                __nv_bfloat16 h3 = __float2bfloat16(v.w);
                __nv_bfloat16 l0 = __float2bfloat16(v.x - __bfloat162float(h0));
                __nv_bfloat16 l1 = __float2bfloat16(v.y - __bfloat162float(h1));
                __nv_bfloat16 l2 = __float2bfloat16(v.z - __bfloat162float(h2));
                __nv_bfloat16 l3 = __float2bfloat16(v.w - __bfloat162float(h3));
                uint2 hv, lv;
                hv.x = (uint32_t)bfbits(h0) | ((uint32_t)bfbits(h1) << 16);
                hv.y = (uint32_t)bfbits(h2) | ((uint32_t)bfbits(h3) << 16);
                lv.x = (uint32_t)bfbits(l0) | ((uint32_t)bfbits(l1) << 16);
                lv.y = (uint32_t)bfbits(l2) | ((uint32_t)bfbits(l3) << 16);
                *(uint2*)(dsthi + row * PITCHB + c5 * 8) = hv;
                *(uint2*)(dstlo + row * PITCHB + c5 * 8) = lv;
            }
            BAR_ARRIVE(1 + b);                     // full[b]
        }
    } else {
        // ================= CONSUMER (warps 0-7, 256 threads) =================
        int g = lane >> 2, tid4 = lane & 3;
        int mrow = (wid & 1) * 64;
        int ncol = (wid >> 1) * 32;
        uint32_t lrow = (uint32_t)(lane & 15);
        uint32_t lcol = (uint32_t)((lane >> 4) << 3);
        uint32_t brow = (uint32_t)(lane & 7);
        uint32_t bk   = (uint32_t)(((lane >> 3) & 1) << 3);

        int i = 0;
        for (int tile = blockIdx.x; tile < NTILES; tile += GRID, i++) {
            int b = i & 1;
            BAR_SYNC(1 + b);                       // wait full[b]
            uint32_t xh = sbXhi[b], xl = sbXlo[b];

            float acc[4][4][4];
#pragma unroll
            for (int ii = 0; ii < 4; ii++)
#pragma unroll
                for (int j = 0; j < 4; j++)
#pragma unroll
                    for (int e = 0; e < 4; e++) acc[ii][j][e] = 0.0f;

#pragma unroll
            for (int ks = 0; ks < 8; ks++) {
                uint32_t Ah[4][4], Al[4][4];
#pragma unroll
                for (int ii = 0; ii < 4; ii++) {
                    uint32_t off = (uint32_t)(mrow + ii * 16 + lrow) * PITCHB +
                                   (uint32_t)(ks * 16 + lcol) * 2;
                    LDSM4(Ah[ii], xh + off);
                    LDSM4(Al[ii], xl + off);
                }
                uint32_t Bh[4][2], Bl[4][2];
#pragma unroll
                for (int j = 0; j < 4; j++) {
                    uint32_t boff = (uint32_t)(ncol + j * 8 + brow) * PITCHB +
                                    (uint32_t)(ks * 16 + bk) * 2;
                    LDSM2(Bh[j], sbWhi + boff);
                    LDSM2(Bl[j], sbWlo + boff);
                }
#pragma unroll
                for (int ii = 0; ii < 4; ii++)
#pragma unroll
                    for (int j = 0; j < 4; j++) MMA16816(acc[ii][j], Ah[ii], Bh[j]);
#pragma unroll
                for (int ii = 0; ii < 4; ii++)
#pragma unroll
                    for (int j = 0; j < 4; j++) MMA16816(acc[ii][j], Ah[ii], Bl[j]);
#pragma unroll
                for (int ii = 0; ii < 4; ii++)
#pragma unroll
                    for (int j = 0; j < 4; j++) MMA16816(acc[ii][j], Al[ii], Bh[j]);
            }
            BAR_ARRIVE(3 + b);                     // empty[b] (reads done)

            float* yt = y + (size_t)tile * DIM * DIM;
#pragma unroll
            for (int ii = 0; ii < 4; ii++) {
                int row0 = mrow + ii * 16 + g;
#pragma unroll
                for (int j = 0; j < 4; j++) {
                    int cb = ncol + j * 8 + tid4 * 2;
                    float2 v0, v1;
                    v0.x = acc[ii][j][0]; v0.y = acc[ii][j][1];
                    v1.x = acc[ii][j][2]; v1.y = acc[ii][j][3];
                    __stcs((float2*)(yt + (size_t)row0 * DIM + cb), v0);
                    __stcs((float2*)(yt + (size_t)(row0 + 8) * DIM + cb), v1);
                }
            }
        }
    }
}

// ---------------------------------------------------------------------------
// Launch
// ---------------------------------------------------------------------------
extern "C" void kernel_launch(void* const* d_in, const int* in_sizes, int n_in,
                              void* d_out, int out_size) {
    const float* x    = (const float*)d_in[0];   // [BATCH, DIM]
    const float* V    = (const float*)d_in[1];   // [DIM, DIM] (v_i = columns)
    const float* sc   = (const float*)d_in[2];   // [1]
    const float* diag = (const float*)d_in[3];   // [DIM]
    float* out = (float*)d_out;

    cudaFuncSetAttribute(build_w_kernel,
                         cudaFuncAttributeMaxDynamicSharedMemorySize, BW_SMEM);
    cudaFuncSetAttribute(gemm_kernel,
                         cudaFuncAttributeMaxDynamicSharedMemorySize, SMEM_BYTES);

    build_w_kernel<<<4, 256, BW_SMEM>>>(V, sc, diag, out, out_size);
    gemm_kernel<<<GRID, 384, SMEM_BYTES>>>(x, out);
}

// round 12
// speedup vs baseline: 1.3252x; 1.1970x over previous
#include <cuda_runtime.h>
#include <cuda_fp16.h>
#include <cstdint>

#define DIM    128
#define BATCH  1048576
#define NTILES (BATCH / DIM)   // 8192
#define GRID   152
#define PITCHB 272             // fp16 smem row pitch (17 x 16B -> LDSM conflict-free)

// ---------------------------------------------------------------------------
// helpers
// ---------------------------------------------------------------------------
__device__ __forceinline__ uint32_t smem_u32(const void* p) {
    uint32_t a;
    asm("{ .reg .u64 t; cvta.to.shared.u64 t, %1; cvt.u32.u64 %0, t; }"
        : "=r"(a) : "l"(p));
    return a;
}

__device__ __forceinline__ unsigned short hbits(__half h) {
    return *reinterpret_cast<unsigned short*>(&h);
}

// fp16 MMA, fp32 accumulate (base PTX ISA; compiles at compute_103)
#define MMA16816(d, a, b)                                                        \
    asm volatile(                                                                \
        "mma.sync.aligned.m16n8k16.row.col.f32.f16.f16.f32 "                     \
        "{%0,%1,%2,%3}, {%4,%5,%6,%7}, {%8,%9}, {%0,%1,%2,%3};"                  \
        : "+f"((d)[0]), "+f"((d)[1]), "+f"((d)[2]), "+f"((d)[3])                 \
        : "r"((a)[0]), "r"((a)[1]), "r"((a)[2]), "r"((a)[3]),                    \
          "r"((b)[0]), "r"((b)[1]))

#define LDSM4(r, addr)                                                           \
    asm volatile("ldmatrix.sync.aligned.m8n8.x4.shared.b16 {%0,%1,%2,%3}, [%4];" \
                 : "=r"((r)[0]), "=r"((r)[1]), "=r"((r)[2]), "=r"((r)[3])        \
                 : "r"(addr))

#define LDSM2(r, addr)                                                           \
    asm volatile("ldmatrix.sync.aligned.m8n8.x2.shared.b16 {%0,%1}, [%2];"       \
                 : "=r"((r)[0]), "=r"((r)[1])                                    \
                 : "r"(addr))

// named producer/consumer barriers (count = all 384 threads)
#define BAR_SYNC(id)   asm volatile("bar.sync %0, 384;"   :: "r"(id) : "memory")
#define BAR_ARRIVE(id) asm volatile("bar.arrive %0, 384;" :: "r"(id) : "memory")

// ---------------------------------------------------------------------------
// Fused kernel: per-CTA redundant W build (Householder scan) + persistent
// producer/consumer GEMM  y = x @ W with x split into fp16 hi+lo against
// fp16 W:  y = (xh + xl) @ Wh  (error = W's fp16 rounding only, ~2.8e-4).
//
// 384 threads: warps 0-7 consumers (64M x 32N warp tiles, 2-product MMA),
// warps 8-11 producers (LDG fp32 -> fp16 hi/lo split -> STS, double buffer).
// ---------------------------------------------------------------------------
#define SM_XHI0 0
#define SM_XLO0 34816
#define SM_XHI1 69632
#define SM_XLO1 104448
#define SM_W    139264
#define SMEM_BYTES 174080

#define VPITCH 132   // fp32 scratch pitch for V columns (528B = 33*16, aligned)

__global__ void __launch_bounds__(384, 1)
fused_kernel(const float* __restrict__ x, const float* __restrict__ V,
             const float* __restrict__ scale, const float* __restrict__ diag,
             float* __restrict__ y, int out_size) {
    extern __shared__ char sm[];
    uint32_t sb = smem_u32(sm);
    uint32_t sbXhi[2] = {sb + SM_XHI0, sb + SM_XHI1};
    uint32_t sbXlo[2] = {sb + SM_XLO0, sb + SM_XLO1};
    uint32_t sbW = sb + SM_W;

    int t = threadIdx.x, wid = t >> 5, lane = t & 31;

    // ======================================================================
    // Phase 0: build W = Q diag s in this CTA's smem (scratch = X region).
    // Threads 0-255: 2 threads per Q row (row = t>>1, 64 floats each) so ALL
    // 128 rows are covered in one CTA (R11 bug: 8 thr/row covered only 32).
    // ======================================================================
    {
        float* sv = (float*)sm;              // sv[col*VPITCH + row] = vhat
        __shared__ float s_invn[DIM];

        // load V transposed (all 384 threads)
        for (int idx = t; idx < DIM * DIM; idx += 384) {
            int r0 = idx >> 7, c0 = idx & 127;
            sv[c0 * VPITCH + r0] = V[idx];
        }
        __syncthreads();

        // inverse norms
        if (t < DIM) {
            float ss = 0.0f;
            const float* c = sv + t * VPITCH;
#pragma unroll 8
            for (int j = 0; j < DIM; j++) ss += c[j] * c[j];
            s_invn[t] = 1.0f / (sqrtf(ss) + 1e-8f);
        }
        __syncthreads();

        // normalize columns in place
        for (int idx = t; idx < DIM * DIM; idx += 384) {
            int r0 = idx & 127, c0 = idx >> 7;
            sv[c0 * VPITCH + r0] *= s_invn[c0];
        }
        __syncthreads();

        // sequential reflections on threads 0-255 (warps 8-11 idle; no syncs
        // inside the loop). 2 threads/row: row = t>>1, h = t&1 (64-col half).
        if (t < 256) {
            int row = t >> 1;
            int h   = t & 1;
            float q[64];
#pragma unroll
            for (int j = 0; j < 64; j++) q[j] = 0.0f;
            {
                int c0 = h * 64;
                if (row >= c0 && row < c0 + 64) q[row - c0] = 1.0f;
            }

            for (int i = 0; i < DIM; i++) {
                const float4* vb = (const float4*)(sv + i * VPITCH + h * 64);
                float4 v4[16];
#pragma unroll
                for (int j4 = 0; j4 < 16; j4++) v4[j4] = vb[j4];

                float d0 = 0.f, d1 = 0.f, d2 = 0.f, d3 = 0.f;
#pragma unroll
                for (int j4 = 0; j4 < 16; j4++) {
                    d0 += q[4 * j4 + 0] * v4[j4].x;
                    d1 += q[4 * j4 + 1] * v4[j4].y;
                    d2 += q[4 * j4 + 2] * v4[j4].z;
                    d3 += q[4 * j4 + 3] * v4[j4].w;
                }
                float dp = (d0 + d1) + (d2 + d3);
                dp += __shfl_xor_sync(0xffffffffu, dp, 1);   // combine halves
                float coef = 2.0f * dp;                       // Q -= 2(Qv)v^T
#pragma unroll
                for (int j4 = 0; j4 < 16; j4++) {
                    q[4 * j4 + 0] -= coef * v4[j4].x;
                    q[4 * j4 + 1] -= coef * v4[j4].y;
                    q[4 * j4 + 2] -= coef * v4[j4].z;
                    q[4 * j4 + 3] -= coef * v4[j4].w;
                }
            }

            // store W_B[n][k]: n = column c, k = row.  W[k][n]=Q[k][n]*diag*s
            float s = scale[0];
#pragma unroll
            for (int j = 0; j < 64; j++) {
                int c = h * 64 + j;
                float w = q[j] * diag[c] * s;
                *(__half*)(sm + SM_W + c * PITCHB + row * 2) = __float2half_rn(w);
            }

            if (blockIdx.x == 0 && t == 0 && out_size > BATCH * DIM) {
                float ld = 0.0f;
                for (int c = 0; c < DIM; c++) ld += logf(fabsf(diag[c] * s) + 1e-8f);
                y[(size_t)BATCH * DIM] = ld;
            }
        }
        __syncthreads();   // W ready; sv scratch dead -> X buffers free
    }

    // ======================================================================
    // Phase 1: persistent producer/consumer GEMM pipeline
    // ======================================================================
    if (wid >= 8) {
        // ---------------- PRODUCER (warps 8-11, 128 threads) ----------------
        int pt = t - 256;                 // 0..127
        int i = 0;
        for (int tile = blockIdx.x; tile < NTILES; tile += GRID, i++) {
            int b = i & 1;
            const float4* src = (const float4*)(x + (size_t)tile * DIM * DIM);
            float4 f[32];
#pragma unroll
            for (int c = 0; c < 32; c++) f[c] = __ldcs(src + c * 128 + pt);

            if (i >= 2) BAR_SYNC(3 + b);           // wait empty[b]

            char* dsthi = sm + (b ? SM_XHI1 : SM_XHI0);
            char* dstlo = sm + (b ? SM_XLO1 : SM_XLO0);
#pragma unroll
            for (int c = 0; c < 32; c++) {
                int idx = c * 128 + pt;
                int row = idx >> 5, c5 = idx & 31;
                float4 v = f[c];
                __half h0 = __float2half_rn(v.x);
                __half h1 = __float2half_rn(v.y);
                __half h2 = __float2half_rn(v.z);
                __half h3 = __float2half_rn(v.w);
                __half l0 = __float2half_rn(v.x - __half2float(h0));
                __half l1 = __float2half_rn(v.y - __half2float(h1));
                __half l2 = __float2half_rn(v.z - __half2float(h2));
                __half l3 = __float2half_rn(v.w - __half2float(h3));
                uint2 hv, lv;
                hv.x = (uint32_t)hbits(h0) | ((uint32_t)hbits(h1) << 16);
                hv.y = (uint32_t)hbits(h2) | ((uint32_t)hbits(h3) << 16);
                lv.x = (uint32_t)hbits(l0) | ((uint32_t)hbits(l1) << 16);
                lv.y = (uint32_t)hbits(l2) | ((uint32_t)hbits(l3) << 16);
                *(uint2*)(dsthi + row * PITCHB + c5 * 8) = hv;
                *(uint2*)(dstlo + row * PITCHB + c5 * 8) = lv;
            }
            BAR_ARRIVE(1 + b);                     // full[b]
        }
    } else {
        // ---------------- CONSUMER (warps 0-7, 256 threads) ----------------
        int g = lane >> 2, tid4 = lane & 3;
        int mrow = (wid & 1) * 64;
        int ncol = (wid >> 1) * 32;
        uint32_t lrow = (uint32_t)(lane & 15);
        uint32_t lcol = (uint32_t)((lane >> 4) << 3);
        uint32_t brow = (uint32_t)(lane & 7);
        uint32_t bk   = (uint32_t)(((lane >> 3) & 1) << 3);

        int i = 0;
        for (int tile = blockIdx.x; tile < NTILES; tile += GRID, i++) {
            int b = i & 1;
            BAR_SYNC(1 + b);                       // wait full[b]
            uint32_t xh = sbXhi[b], xl = sbXlo[b];

            float acc[4][4][4];
#pragma unroll
            for (int ii = 0; ii < 4; ii++)
#pragma unroll
                for (int j = 0; j < 4; j++)
#pragma unroll
                    for (int e = 0; e < 4; e++) acc[ii][j][e] = 0.0f;

#pragma unroll
            for (int ks = 0; ks < 8; ks++) {
                uint32_t Ah[4][4], Al[4][4];
#pragma unroll
                for (int ii = 0; ii < 4; ii++) {
                    uint32_t off = (uint32_t)(mrow + ii * 16 + lrow) * PITCHB +
                                   (uint32_t)(ks * 16 + lcol) * 2;
                    LDSM4(Ah[ii], xh + off);
                    LDSM4(Al[ii], xl + off);
                }
                uint32_t Bh[4][2];
#pragma unroll
                for (int j = 0; j < 4; j++) {
                    uint32_t boff = (uint32_t)(ncol + j * 8 + brow) * PITCHB +
                                    (uint32_t)(ks * 16 + bk) * 2;
                    LDSM2(Bh[j], sbW + boff);
                }
#pragma unroll
                for (int ii = 0; ii < 4; ii++)
#pragma unroll
                    for (int j = 0; j < 4; j++) MMA16816(acc[ii][j], Ah[ii], Bh[j]);
#pragma unroll
                for (int ii = 0; ii < 4; ii++)
#pragma unroll
                    for (int j = 0; j < 4; j++) MMA16816(acc[ii][j], Al[ii], Bh[j]);
            }
            BAR_ARRIVE(3 + b);                     // empty[b] (reads done)

            float* yt = y + (size_t)tile * DIM * DIM;
#pragma unroll
            for (int ii = 0; ii < 4; ii++) {
                int row0 = mrow + ii * 16 + g;
#pragma unroll
                for (int j = 0; j < 4; j++) {
                    int cb = ncol + j * 8 + tid4 * 2;
                    float2 v0, v1;
                    v0.x = acc[ii][j][0]; v0.y = acc[ii][j][1];
                    v1.x = acc[ii][j][2]; v1.y = acc[ii][j][3];
                    __stcs((float2*)(yt + (size_t)row0 * DIM + cb), v0);
                    __stcs((float2*)(yt + (size_t)(row0 + 8) * DIM + cb), v1);
                }
            }
        }
    }
}

// ---------------------------------------------------------------------------
// Launch
// ---------------------------------------------------------------------------
extern "C" void kernel_launch(void* const* d_in, const int* in_sizes, int n_in,
                              void* d_out, int out_size) {
    const float* x    = (const float*)d_in[0];   // [BATCH, DIM]
    const float* V    = (const float*)d_in[1];   // [DIM, DIM] (v_i = columns)
    const float* sc   = (const float*)d_in[2];   // [1]
    const float* diag = (const float*)d_in[3];   // [DIM]
    float* out = (float*)d_out;

    cudaFuncSetAttribute(fused_kernel,
                         cudaFuncAttributeMaxDynamicSharedMemorySize, SMEM_BYTES);
    fused_kernel<<<GRID, 384, SMEM_BYTES>>>(x, V, sc, diag, out, out_size);
}

// round 13
// speedup vs baseline: 1.6681x; 1.2588x over previous
#include <cuda_runtime.h>
#include <cuda_fp16.h>
#include <cstdint>

#define DIM    128
#define BATCH  1048576
#define NTILES (BATCH / DIM)   // 8192
#define GRID   152
#define PITCHB 272             // fp16 smem row pitch (17 x 16B -> LDSM conflict-free)

// ---------------------------------------------------------------------------
// helpers
// ---------------------------------------------------------------------------
__device__ __forceinline__ uint32_t smem_u32(const void* p) {
    uint32_t a;
    asm("{ .reg .u64 t; cvta.to.shared.u64 t, %1; cvt.u32.u64 %0, t; }"
        : "=r"(a) : "l"(p));
    return a;
}

__device__ __forceinline__ unsigned short hbits(__half h) {
    return *reinterpret_cast<unsigned short*>(&h);
}

// fp16 MMA, fp32 accumulate (base PTX ISA; compiles at compute_103)
#define MMA16816(d, a, b)                                                        \
    asm volatile(                                                                \
        "mma.sync.aligned.m16n8k16.row.col.f32.f16.f16.f32 "                     \
        "{%0,%1,%2,%3}, {%4,%5,%6,%7}, {%8,%9}, {%0,%1,%2,%3};"                  \
        : "+f"((d)[0]), "+f"((d)[1]), "+f"((d)[2]), "+f"((d)[3])                 \
        : "r"((a)[0]), "r"((a)[1]), "r"((a)[2]), "r"((a)[3]),                    \
          "r"((b)[0]), "r"((b)[1]))

#define LDSM4(r, addr)                                                           \
    asm volatile("ldmatrix.sync.aligned.m8n8.x4.shared.b16 {%0,%1,%2,%3}, [%4];" \
                 : "=r"((r)[0]), "=r"((r)[1]), "=r"((r)[2]), "=r"((r)[3])        \
                 : "r"(addr))

#define LDSM2(r, addr)                                                           \
    asm volatile("ldmatrix.sync.aligned.m8n8.x2.shared.b16 {%0,%1}, [%2];"       \
                 : "=r"((r)[0]), "=r"((r)[1])                                    \
                 : "r"(addr))

// named producer/consumer barriers (count = all 384 threads)
#define BAR_SYNC(id)   asm volatile("bar.sync %0, 384;"   :: "r"(id) : "memory")
#define BAR_ARRIVE(id) asm volatile("bar.arrive %0, 384;" :: "r"(id) : "memory")

// ---------------------------------------------------------------------------
// Fused kernel: per-CTA redundant W build (Householder scan) + persistent
// producer/consumer GEMM  y = fp16(x) @ fp16(W), fp32 accumulate.
// Error model (validated R12): W rounding 2.1e-4 + x rounding 1.4e-4
// in quadrature ~= 2.5e-4 << 1e-3 threshold.
//
// 384 threads: warps 0-7 consumers (64M x 32N warp tiles, single-product
// fp16 MMA), warps 8-11 producers (LDG fp32 -> fp16 -> STS, double buffer).
// ---------------------------------------------------------------------------
#define SM_XH0 0
#define SM_XH1 34816
#define SM_W   69632
#define SMEM_BYTES 104448

#define VPITCH 132   // fp32 scratch pitch for V columns (528B = 33*16, aligned)

__global__ void __launch_bounds__(384, 1)
fused_kernel(const float* __restrict__ x, const float* __restrict__ V,
             const float* __restrict__ scale, const float* __restrict__ diag,
             float* __restrict__ y, int out_size) {
    extern __shared__ char sm[];
    uint32_t sb = smem_u32(sm);
    uint32_t sbXh[2] = {sb + SM_XH0, sb + SM_XH1};
    uint32_t sbW = sb + SM_W;

    int t = threadIdx.x, wid = t >> 5, lane = t & 31;

    // ======================================================================
    // Phase 0: build W = Q diag s in this CTA's smem.
    // sv scratch occupies [0, 67584) = X buffers; W region [69632,...) is
    // disjoint, so W stores during the scan don't clobber sv.
    // Threads 0-255: 2 threads per Q row (row = t>>1, 64 floats each).
    // ======================================================================
    {
        float* sv = (float*)sm;              // sv[col*VPITCH + row] = vhat
        __shared__ float s_invn[DIM];

        for (int idx = t; idx < DIM * DIM; idx += 384) {
            int r0 = idx >> 7, c0 = idx & 127;
            sv[c0 * VPITCH + r0] = V[idx];
        }
        __syncthreads();

        if (t < DIM) {
            float ss = 0.0f;
            const float* c = sv + t * VPITCH;
#pragma unroll 8
            for (int j = 0; j < DIM; j++) ss += c[j] * c[j];
            s_invn[t] = 1.0f / (sqrtf(ss) + 1e-8f);
        }
        __syncthreads();

        for (int idx = t; idx < DIM * DIM; idx += 384) {
            int r0 = idx & 127, c0 = idx >> 7;
            sv[c0 * VPITCH + r0] *= s_invn[c0];
        }
        __syncthreads();

        if (t < 256) {
            int row = t >> 1;
            int h   = t & 1;
            float q[64];
#pragma unroll
            for (int j = 0; j < 64; j++) q[j] = 0.0f;
            {
                int c0 = h * 64;
                if (row >= c0 && row < c0 + 64) q[row - c0] = 1.0f;
            }

            for (int i = 0; i < DIM; i++) {
                const float4* vb = (const float4*)(sv + i * VPITCH + h * 64);
                float4 v4[16];
#pragma unroll
                for (int j4 = 0; j4 < 16; j4++) v4[j4] = vb[j4];

                float d0 = 0.f, d1 = 0.f, d2 = 0.f, d3 = 0.f;
#pragma unroll
                for (int j4 = 0; j4 < 16; j4++) {
                    d0 += q[4 * j4 + 0] * v4[j4].x;
                    d1 += q[4 * j4 + 1] * v4[j4].y;
                    d2 += q[4 * j4 + 2] * v4[j4].z;
                    d3 += q[4 * j4 + 3] * v4[j4].w;
                }
                float dp = (d0 + d1) + (d2 + d3);
                dp += __shfl_xor_sync(0xffffffffu, dp, 1);   // combine halves
                float coef = 2.0f * dp;                       // Q -= 2(Qv)v^T
#pragma unroll
                for (int j4 = 0; j4 < 16; j4++) {
                    q[4 * j4 + 0] -= coef * v4[j4].x;
                    q[4 * j4 + 1] -= coef * v4[j4].y;
                    q[4 * j4 + 2] -= coef * v4[j4].z;
                    q[4 * j4 + 3] -= coef * v4[j4].w;
                }
            }

            // store W_B[n][k]: n = col c, k = row.  W[k][n] = Q[k][n]*diag*s
            float s = scale[0];
#pragma unroll
            for (int j = 0; j < 64; j++) {
                int c = h * 64 + j;
                float w = q[j] * diag[c] * s;
                *(__half*)(sm + SM_W + c * PITCHB + row * 2) = __float2half_rn(w);
            }

            if (blockIdx.x == 0 && t == 0 && out_size > BATCH * DIM) {
                float ld = 0.0f;
                for (int c = 0; c < DIM; c++) ld += logf(fabsf(diag[c] * s) + 1e-8f);
                y[(size_t)BATCH * DIM] = ld;
            }
        }
        __syncthreads();   // W ready; sv scratch dead -> X buffers free
    }

    // ======================================================================
    // Phase 1: persistent producer/consumer GEMM pipeline
    // ======================================================================
    if (wid >= 8) {
        // ---------------- PRODUCER (warps 8-11, 128 threads) ----------------
        int pt = t - 256;                 // 0..127
        int i = 0;
        for (int tile = blockIdx.x; tile < NTILES; tile += GRID, i++) {
            int b = i & 1;
            const float4* src = (const float4*)(x + (size_t)tile * DIM * DIM);
            float4 f[32];
#pragma unroll
            for (int c = 0; c < 32; c++) f[c] = __ldcs(src + c * 128 + pt);

            if (i >= 2) BAR_SYNC(3 + b);           // wait empty[b]

            char* dst = sm + (b ? SM_XH1 : SM_XH0);
#pragma unroll
            for (int c = 0; c < 32; c++) {
                int idx = c * 128 + pt;
                int row = idx >> 5, c5 = idx & 31;
                float4 v = f[c];
                __half h0 = __float2half_rn(v.x);
                __half h1 = __float2half_rn(v.y);
                __half h2 = __float2half_rn(v.z);
                __half h3 = __float2half_rn(v.w);
                uint2 hv;
                hv.x = (uint32_t)hbits(h0) | ((uint32_t)hbits(h1) << 16);
                hv.y = (uint32_t)hbits(h2) | ((uint32_t)hbits(h3) << 16);
                *(uint2*)(dst + row * PITCHB + c5 * 8) = hv;
            }
            BAR_ARRIVE(1 + b);                     // full[b]
        }
    } else {
        // ---------------- CONSUMER (warps 0-7, 256 threads) ----------------
        int g = lane >> 2, tid4 = lane & 3;
        int mrow = (wid & 1) * 64;
        int ncol = (wid >> 1) * 32;
        uint32_t lrow = (uint32_t)(lane & 15);
        uint32_t lcol = (uint32_t)((lane >> 4) << 3);
        uint32_t brow = (uint32_t)(lane & 7);
        uint32_t bk   = (uint32_t)(((lane >> 3) & 1) << 3);

        int i = 0;
        for (int tile = blockIdx.x; tile < NTILES; tile += GRID, i++) {
            int b = i & 1;
            BAR_SYNC(1 + b);                       // wait full[b]
            uint32_t xh = sbXh[b];

            float acc[4][4][4];
#pragma unroll
            for (int ii = 0; ii < 4; ii++)
#pragma unroll
                for (int j = 0; j < 4; j++)
#pragma unroll
                    for (int e = 0; e < 4; e++) acc[ii][j][e] = 0.0f;

#pragma unroll
            for (int ks = 0; ks < 8; ks++) {
                uint32_t Ah[4][4];
#pragma unroll
                for (int ii = 0; ii < 4; ii++) {
                    uint32_t off = (uint32_t)(mrow + ii * 16 + lrow) * PITCHB +
                                   (uint32_t)(ks * 16 + lcol) * 2;
                    LDSM4(Ah[ii], xh + off);
                }
                uint32_t Bh[4][2];
#pragma unroll
                for (int j = 0; j < 4; j++) {
                    uint32_t boff = (uint32_t)(ncol + j * 8 + brow) * PITCHB +
                                    (uint32_t)(ks * 16 + bk) * 2;
                    LDSM2(Bh[j], sbW + boff);
                }
#pragma unroll
                for (int ii = 0; ii < 4; ii++)
#pragma unroll
                    for (int j = 0; j < 4; j++) MMA16816(acc[ii][j], Ah[ii], Bh[j]);
            }
            BAR_ARRIVE(3 + b);                     // empty[b] (reads done)

            float* yt = y + (size_t)tile * DIM * DIM;
#pragma unroll
            for (int ii = 0; ii < 4; ii++) {
                int row0 = mrow + ii * 16 + g;
#pragma unroll
                for (int j = 0; j < 4; j++) {
                    int cb = ncol + j * 8 + tid4 * 2;
                    float2 v0, v1;
                    v0.x = acc[ii][j][0]; v0.y = acc[ii][j][1];
                    v1.x = acc[ii][j][2]; v1.y = acc[ii][j][3];
                    __stcs((float2*)(yt + (size_t)row0 * DIM + cb), v0);
                    __stcs((float2*)(yt + (size_t)(row0 + 8) * DIM + cb), v1);
                }
            }
        }
    }
}

// ---------------------------------------------------------------------------
// Launch
// ---------------------------------------------------------------------------
extern "C" void kernel_launch(void* const* d_in, const int* in_sizes, int n_in,
                              void* d_out, int out_size) {
    const float* x    = (const float*)d_in[0];   // [BATCH, DIM]
    const float* V    = (const float*)d_in[1];   // [DIM, DIM] (v_i = columns)
    const float* sc   = (const float*)d_in[2];   // [1]
    const float* diag = (const float*)d_in[3];   // [DIM]
    float* out = (float*)d_out;

    cudaFuncSetAttribute(fused_kernel,
                         cudaFuncAttributeMaxDynamicSharedMemorySize, SMEM_BYTES);
    fused_kernel<<<GRID, 384, SMEM_BYTES>>>(x, V, sc, diag, out, out_size);
}

// round 14
// speedup vs baseline: 1.6702x; 1.0012x over previous
#include <cuda_runtime.h>
#include <cuda_fp16.h>
#include <cstdint>

#define DIM    128
#define BATCH  1048576
#define NTILES (BATCH / DIM)   // 8192
#define GRID   152
#define PITCHB 272             // fp16 smem row pitch (17 x 16B -> LDSM conflict-free)
#define STAGES 4

// ---------------------------------------------------------------------------
// helpers
// ---------------------------------------------------------------------------
__device__ __forceinline__ uint32_t smem_u32(const void* p) {
    uint32_t a;
    asm("{ .reg .u64 t; cvta.to.shared.u64 t, %1; cvt.u32.u64 %0, t; }"
        : "=r"(a) : "l"(p));
    return a;
}

// fp16 MMA, fp32 accumulate (base PTX ISA; compiles at compute_103)
#define MMA16816(d, a, b)                                                        \
    asm volatile(                                                                \
        "mma.sync.aligned.m16n8k16.row.col.f32.f16.f16.f32 "                     \
        "{%0,%1,%2,%3}, {%4,%5,%6,%7}, {%8,%9}, {%0,%1,%2,%3};"                  \
        : "+f"((d)[0]), "+f"((d)[1]), "+f"((d)[2]), "+f"((d)[3])                 \
        : "r"((a)[0]), "r"((a)[1]), "r"((a)[2]), "r"((a)[3]),                    \
          "r"((b)[0]), "r"((b)[1]))

#define LDSM4(r, addr)                                                           \
    asm volatile("ldmatrix.sync.aligned.m8n8.x4.shared.b16 {%0,%1,%2,%3}, [%4];" \
                 : "=r"((r)[0]), "=r"((r)[1]), "=r"((r)[2]), "=r"((r)[3])        \
                 : "r"(addr))

// pack 2 fp32 -> f16x2 in one instruction (d.hi = cvt(a), d.lo = cvt(b))
#define CVT_F16X2(d, hi, lo)                                                     \
    asm("cvt.rn.f16x2.f32 %0, %1, %2;" : "=r"(d) : "f"(hi), "f"(lo))

// named producer/consumer barriers (count = all 384 threads)
#define BAR_SYNC(id)   asm volatile("bar.sync %0, 384;"   :: "r"(id) : "memory")
#define BAR_ARRIVE(id) asm volatile("bar.arrive %0, 384;" :: "r"(id) : "memory")

// ---------------------------------------------------------------------------
// Fused kernel: per-CTA redundant W build (Householder scan) + persistent
// producer/consumer GEMM  y = fp16(x) @ fp16(W), fp32 accumulate.
// rel_err ~2.9e-4 (W fp16 rounding + x fp16 rounding; validated R12/R13).
//
// 384 threads: warps 0-7 consumers (64M x 32N warp tiles), warps 8-11
// producers (LDG fp32 -> f16x2 cvt -> STS). 4-stage X ring buffer.
// ---------------------------------------------------------------------------
#define SM_STAGE(s) ((s) * 34816)
#define SM_W        139264
#define SMEM_BYTES  174080

#define VPITCH 132   // fp32 scratch pitch for V columns (528B = 33*16, aligned)

__global__ void __launch_bounds__(384, 1)
fused_kernel(const float* __restrict__ x, const float* __restrict__ V,
             const float* __restrict__ scale, const float* __restrict__ diag,
             float* __restrict__ y, int out_size) {
    extern __shared__ char sm[];
    uint32_t sb = smem_u32(sm);
    uint32_t sbW = sb + SM_W;

    int t = threadIdx.x, wid = t >> 5, lane = t & 31;

    // ======================================================================
    // Phase 0: build W = Q diag s in this CTA's smem.
    // sv scratch uses [0, 67584) = stages 0-1; W region is disjoint.
    // Threads 0-255: 2 threads per Q row (row = t>>1, 64 floats each).
    // ======================================================================
    {
        float* sv = (float*)sm;              // sv[col*VPITCH + row] = vhat
        __shared__ float s_invn[DIM];

        for (int idx = t; idx < DIM * DIM; idx += 384) {
            int r0 = idx >> 7, c0 = idx & 127;
            sv[c0 * VPITCH + r0] = V[idx];
        }
        __syncthreads();

        if (t < DIM) {
            float ss = 0.0f;
            const float* c = sv + t * VPITCH;
#pragma unroll 8
            for (int j = 0; j < DIM; j++) ss += c[j] * c[j];
            s_invn[t] = 1.0f / (sqrtf(ss) + 1e-8f);
        }
        __syncthreads();

        for (int idx = t; idx < DIM * DIM; idx += 384) {
            int r0 = idx & 127, c0 = idx >> 7;
            sv[c0 * VPITCH + r0] *= s_invn[c0];
        }
        __syncthreads();

        if (t < 256) {
            int row = t >> 1;
            int h   = t & 1;
            float q[64];
#pragma unroll
            for (int j = 0; j < 64; j++) q[j] = 0.0f;
            {
                int c0 = h * 64;
                if (row >= c0 && row < c0 + 64) q[row - c0] = 1.0f;
            }

            for (int i = 0; i < DIM; i++) {
                const float4* vb = (const float4*)(sv + i * VPITCH + h * 64);
                float4 v4[16];
#pragma unroll
                for (int j4 = 0; j4 < 16; j4++) v4[j4] = vb[j4];

                float d0 = 0.f, d1 = 0.f, d2 = 0.f, d3 = 0.f;
#pragma unroll
                for (int j4 = 0; j4 < 16; j4++) {
                    d0 += q[4 * j4 + 0] * v4[j4].x;
                    d1 += q[4 * j4 + 1] * v4[j4].y;
                    d2 += q[4 * j4 + 2] * v4[j4].z;
                    d3 += q[4 * j4 + 3] * v4[j4].w;
                }
                float dp = (d0 + d1) + (d2 + d3);
                dp += __shfl_xor_sync(0xffffffffu, dp, 1);   // combine halves
                float coef = 2.0f * dp;                       // Q -= 2(Qv)v^T
#pragma unroll
                for (int j4 = 0; j4 < 16; j4++) {
                    q[4 * j4 + 0] -= coef * v4[j4].x;
                    q[4 * j4 + 1] -= coef * v4[j4].y;
                    q[4 * j4 + 2] -= coef * v4[j4].z;
                    q[4 * j4 + 3] -= coef * v4[j4].w;
                }
            }

            // store W_B[n][k]: n = col c, k = row.  W[k][n] = Q[k][n]*diag*s
            float s = scale[0];
#pragma unroll
            for (int j = 0; j < 64; j++) {
                int c = h * 64 + j;
                float w = q[j] * diag[c] * s;
                *(__half*)(sm + SM_W + c * PITCHB + row * 2) = __float2half_rn(w);
            }

            if (blockIdx.x == 0 && t == 0 && out_size > BATCH * DIM) {
                float ld = 0.0f;
                for (int c = 0; c < DIM; c++) ld += logf(fabsf(diag[c] * s) + 1e-8f);
                y[(size_t)BATCH * DIM] = ld;
            }
        }
        __syncthreads();   // W ready; sv scratch dead -> X stages free
    }

    // ======================================================================
    // Phase 1: persistent producer/consumer GEMM, 4-stage ring.
    // barriers: full[s] = 1+s, empty[s] = 5+s  (s = 0..3)
    // ======================================================================
    if (wid >= 8) {
        // ---------------- PRODUCER (warps 8-11, 128 threads) ----------------
        int pt = t - 256;                 // 0..127
        int i = 0;
        for (int tile = blockIdx.x; tile < NTILES; tile += GRID, i++) {
            int s = i & (STAGES - 1);
            const float4* src = (const float4*)(x + (size_t)tile * DIM * DIM);
            float4 f[32];
#pragma unroll
            for (int c = 0; c < 32; c++) f[c] = __ldcs(src + c * 128 + pt);

            if (i >= STAGES) BAR_SYNC(5 + s);      // wait empty[s]

            char* dst = sm + SM_STAGE(s);
#pragma unroll
            for (int c = 0; c < 32; c++) {
                int idx = c * 128 + pt;
                int row = idx >> 5, c5 = idx & 31;
                float4 v = f[c];
                uint2 hv;
                CVT_F16X2(hv.x, v.y, v.x);
                CVT_F16X2(hv.y, v.w, v.z);
                *(uint2*)(dst + row * PITCHB + c5 * 8) = hv;
            }
            BAR_ARRIVE(1 + s);                     // full[s]
        }
    } else {
        // ---------------- CONSUMER (warps 0-7, 256 threads) ----------------
        int g = lane >> 2, tid4 = lane & 3;
        int mrow = (wid & 1) * 64;
        int ncol = (wid >> 1) * 32;
        uint32_t lrow = (uint32_t)(lane & 15);
        uint32_t lcol = (uint32_t)((lane >> 4) << 3);
        // B ldmatrix.x4 over a 16-n-row pair: lanes 0-7 m0(k lo), 8-15 m1(k hi),
        // 16-23 m2(n+8, k lo), 24-31 m3(n+8, k hi)
        uint32_t bn = (uint32_t)(((lane >> 4) << 3) + (lane & 7));
        uint32_t bk = (uint32_t)(((lane >> 3) & 1) << 3);

        int i = 0;
        for (int tile = blockIdx.x; tile < NTILES; tile += GRID, i++) {
            int s = i & (STAGES - 1);
            BAR_SYNC(1 + s);                       // wait full[s]
            uint32_t xh = sb + SM_STAGE(s);

            float acc[4][4][4];
#pragma unroll
            for (int ii = 0; ii < 4; ii++)
#pragma unroll
                for (int j = 0; j < 4; j++)
#pragma unroll
                    for (int e = 0; e < 4; e++) acc[ii][j][e] = 0.0f;

#pragma unroll
            for (int ks = 0; ks < 8; ks++) {
                uint32_t Ah[4][4];
#pragma unroll
                for (int ii = 0; ii < 4; ii++) {
                    uint32_t off = (uint32_t)(mrow + ii * 16 + lrow) * PITCHB +
                                   (uint32_t)(ks * 16 + lcol) * 2;
                    LDSM4(Ah[ii], xh + off);
                }
                uint32_t Bh[4][2];
#pragma unroll
                for (int jp = 0; jp < 2; jp++) {
                    uint32_t boff = (uint32_t)(ncol + jp * 16 + bn) * PITCHB +
                                    (uint32_t)(ks * 16 + bk) * 2;
                    uint32_t Bq[4];
                    LDSM4(Bq, sbW + boff);
                    Bh[jp * 2 + 0][0] = Bq[0]; Bh[jp * 2 + 0][1] = Bq[1];
                    Bh[jp * 2 + 1][0] = Bq[2]; Bh[jp * 2 + 1][1] = Bq[3];
                }
#pragma unroll
                for (int ii = 0; ii < 4; ii++)
#pragma unroll
                    for (int j = 0; j < 4; j++) MMA16816(acc[ii][j], Ah[ii], Bh[j]);
            }
            BAR_ARRIVE(5 + s);                     // empty[s] (reads done)

            float* yt = y + (size_t)tile * DIM * DIM;
#pragma unroll
            for (int ii = 0; ii < 4; ii++) {
                int row0 = mrow + ii * 16 + g;
#pragma unroll
                for (int j = 0; j < 4; j++) {
                    int cb = ncol + j * 8 + tid4 * 2;
                    float2 v0, v1;
                    v0.x = acc[ii][j][0]; v0.y = acc[ii][j][1];
                    v1.x = acc[ii][j][2]; v1.y = acc[ii][j][3];
                    __stcs((float2*)(yt + (size_t)row0 * DIM + cb), v0);
                    __stcs((float2*)(yt + (size_t)(row0 + 8) * DIM + cb), v1);
                }
            }
        }
    }
}

// ---------------------------------------------------------------------------
// Launch
// ---------------------------------------------------------------------------
extern "C" void kernel_launch(void* const* d_in, const int* in_sizes, int n_in,
                              void* d_out, int out_size) {
    const float* x    = (const float*)d_in[0];   // [BATCH, DIM]
    const float* V    = (const float*)d_in[1];   // [DIM, DIM] (v_i = columns)
    const float* sc   = (const float*)d_in[2];   // [1]
    const float* diag = (const float*)d_in[3];   // [DIM]
    float* out = (float*)d_out;

    cudaFuncSetAttribute(fused_kernel,
                         cudaFuncAttributeMaxDynamicSharedMemorySize, SMEM_BYTES);
    fused_kernel<<<GRID, 384, SMEM_BYTES>>>(x, V, sc, diag, out, out_size);
}

// round 15
// speedup vs baseline: 1.7406x; 1.0422x over previous
#include <cuda_runtime.h>
#include <cuda_fp16.h>
#include <cstdint>

#define DIM    128
#define BATCH  1048576
#define NT64   (BATCH / 64)    // 16384 half-tiles (64 rows each)
#define GRID   152
#define PITCHB 272             // fp16 smem row pitch (17 x 16B -> LDSM conflict-free)
#define STAGES 3
#define STG_BYTES (64 * PITCHB)   // 17408 per stage

// ---------------------------------------------------------------------------
// helpers
// ---------------------------------------------------------------------------
__device__ __forceinline__ uint32_t smem_u32(const void* p) {
    uint32_t a;
    asm("{ .reg .u64 t; cvta.to.shared.u64 t, %1; cvt.u32.u64 %0, t; }"
        : "=r"(a) : "l"(p));
    return a;
}

// fp16 MMA, fp32 accumulate (base PTX ISA; compiles at compute_103)
#define MMA16816(d, a, b)                                                        \
    asm volatile(                                                                \
        "mma.sync.aligned.m16n8k16.row.col.f32.f16.f16.f32 "                     \
        "{%0,%1,%2,%3}, {%4,%5,%6,%7}, {%8,%9}, {%0,%1,%2,%3};"                  \
        : "+f"((d)[0]), "+f"((d)[1]), "+f"((d)[2]), "+f"((d)[3])                 \
        : "r"((a)[0]), "r"((a)[1]), "r"((a)[2]), "r"((a)[3]),                    \
          "r"((b)[0]), "r"((b)[1]))

#define LDSM4(r, addr)                                                           \
    asm volatile("ldmatrix.sync.aligned.m8n8.x4.shared.b16 {%0,%1,%2,%3}, [%4];" \
                 : "=r"((r)[0]), "=r"((r)[1]), "=r"((r)[2]), "=r"((r)[3])        \
                 : "r"(addr))

// pack 2 fp32 -> f16x2 in one instruction
#define CVT_F16X2(d, hi, lo)                                                     \
    asm("cvt.rn.f16x2.f32 %0, %1, %2;" : "=f16x2_dummy_unused" : )
#undef CVT_F16X2
#define CVT_F16X2(d, hi, lo)                                                     \
    asm("cvt.rn.f16x2.f32 %0, %1, %2;" : "=r"(d) : "f"(hi), "f"(lo))

// named stream barriers, 192 participants (4 consumer + 2 producer warps)
#define SBAR_SYNC(id)   asm volatile("bar.sync %0, 192;"   :: "r"(id) : "memory")
#define SBAR_ARRIVE(id) asm volatile("bar.arrive %0, 192;" :: "r"(id) : "memory")

// ---------------------------------------------------------------------------
// Fused kernel: per-CTA redundant W build (Householder scan) + TWO independent
// persistent producer/consumer GEMM streams sharing the W smem tile.
//   y = fp16(x) @ fp16(W), fp32 accumulate (rel_err ~2.9e-4, validated).
//
// 384 threads: warps 0-3 consumers S0, 4-7 consumers S1 (each warp 64Mx32N),
// warps 8-9 producers S0, 10-11 producers S1. 3-stage ring per stream.
// Stream s processes half-tiles  blockIdx*2 + s, step GRID*2 (adjacent in
// memory -> L2 locality between the CTA's two streams).
// ---------------------------------------------------------------------------
#define SM_STAGE(st, s) (((st) * STAGES + (s)) * STG_BYTES)
#define SM_W            (6 * STG_BYTES)          // 104448
#define SMEM_BYTES      (SM_W + 34816)           // 139264

#define VPITCH 132   // fp32 scratch pitch for V columns (528B = 33*16, aligned)

__global__ void __launch_bounds__(384, 1)
fused_kernel(const float* __restrict__ x, const float* __restrict__ V,
             const float* __restrict__ scale, const float* __restrict__ diag,
             float* __restrict__ y, int out_size) {
    extern __shared__ char sm[];
    uint32_t sb = smem_u32(sm);
    uint32_t sbW = sb + SM_W;

    int t = threadIdx.x, wid = t >> 5, lane = t & 31;

    // ======================================================================
    // Phase 0: build W = Q diag s in this CTA's smem.
    // sv scratch uses [0, 67584) inside the stage area [0, 104448); W region
    // is disjoint. Threads 0-255: 2 threads/Q-row (row = t>>1, 64 floats).
    // ======================================================================
    {
        float* sv = (float*)sm;              // sv[col*VPITCH + row] = vhat
        __shared__ float s_invn[DIM];

        for (int idx = t; idx < DIM * DIM; idx += 384) {
            int r0 = idx >> 7, c0 = idx & 127;
            sv[c0 * VPITCH + r0] = V[idx];
        }
        __syncthreads();

        if (t < DIM) {
            float ss = 0.0f;
            const float* c = sv + t * VPITCH;
#pragma unroll 8
            for (int j = 0; j < DIM; j++) ss += c[j] * c[j];
            s_invn[t] = 1.0f / (sqrtf(ss) + 1e-8f);
        }
        __syncthreads();

        for (int idx = t; idx < DIM * DIM; idx += 384) {
            int r0 = idx & 127, c0 = idx >> 7;
            sv[c0 * VPITCH + r0] *= s_invn[c0];
        }
        __syncthreads();

        if (t < 256) {
            int row = t >> 1;
            int h   = t & 1;
            float q[64];
#pragma unroll
            for (int j = 0; j < 64; j++) q[j] = 0.0f;
            {
                int c0 = h * 64;
                if (row >= c0 && row < c0 + 64) q[row - c0] = 1.0f;
            }

            for (int i = 0; i < DIM; i++) {
                const float4* vb = (const float4*)(sv + i * VPITCH + h * 64);
                float4 v4[16];
#pragma unroll
                for (int j4 = 0; j4 < 16; j4++) v4[j4] = vb[j4];

                float d0 = 0.f, d1 = 0.f, d2 = 0.f, d3 = 0.f;
#pragma unroll
                for (int j4 = 0; j4 < 16; j4++) {
                    d0 += q[4 * j4 + 0] * v4[j4].x;
                    d1 += q[4 * j4 + 1] * v4[j4].y;
                    d2 += q[4 * j4 + 2] * v4[j4].z;
                    d3 += q[4 * j4 + 3] * v4[j4].w;
                }
                float dp = (d0 + d1) + (d2 + d3);
                dp += __shfl_xor_sync(0xffffffffu, dp, 1);   // combine halves
                float coef = 2.0f * dp;                       // Q -= 2(Qv)v^T
#pragma unroll
                for (int j4 = 0; j4 < 16; j4++) {
                    q[4 * j4 + 0] -= coef * v4[j4].x;
                    q[4 * j4 + 1] -= coef * v4[j4].y;
                    q[4 * j4 + 2] -= coef * v4[j4].z;
                    q[4 * j4 + 3] -= coef * v4[j4].w;
                }
            }

            // store W_B[n][k]: n = col c, k = row.  W[k][n] = Q[k][n]*diag*s
            float s = scale[0];
#pragma unroll
            for (int j = 0; j < 64; j++) {
                int c = h * 64 + j;
                float w = q[j] * diag[c] * s;
                *(__half*)(sm + SM_W + c * PITCHB + row * 2) = __float2half_rn(w);
            }

            if (blockIdx.x == 0 && t == 0 && out_size > BATCH * DIM) {
                float ld = 0.0f;
                for (int c = 0; c < DIM; c++) ld += logf(fabsf(diag[c] * s) + 1e-8f);
                y[(size_t)BATCH * DIM] = ld;
            }
        }
        __syncthreads();   // W ready; sv scratch dead -> stage buffers free
    }

    // ======================================================================
    // Phase 1: two independent persistent pipelines (streams), 3-stage rings.
    // Barrier ids: stream st: full[s] = 1 + st*6 + s, empty[s] = 4 + st*6 + s
    //   S0: full 1-3, empty 4-6;  S1: full 7-9, empty 10-12.
    // ======================================================================
    if (wid >= 8) {
        // ---------------- PRODUCER (2 warps per stream) ----------------
        int st  = (wid - 8) >> 1;             // stream 0/1
        int pt  = t - 256 - st * 64;          // 0..63 within stream
        int barF = 1 + st * 6, barE = 4 + st * 6;

        int i = 0, s = 0;
        for (int tile = blockIdx.x * 2 + st; tile < NT64; tile += GRID * 2, i++) {
            const float4* src = (const float4*)(x + (size_t)tile * 64 * DIM);
            float4 f[32];
#pragma unroll
            for (int c = 0; c < 32; c++) f[c] = __ldcs(src + c * 64 + pt);

            if (i >= STAGES) SBAR_SYNC(barE + s);    // wait empty[s]

            char* dst = sm + SM_STAGE(st, s);
#pragma unroll
            for (int c = 0; c < 32; c++) {
                int idx = c * 64 + pt;               // float4 chunk in half-tile
                int row = idx >> 5, c5 = idx & 31;
                float4 v = f[c];
                uint2 hv;
                CVT_F16X2(hv.x, v.y, v.x);
                CVT_F16X2(hv.y, v.w, v.z);
                *(uint2*)(dst + row * PITCHB + c5 * 8) = hv;
            }
            SBAR_ARRIVE(barF + s);                   // full[s]
            if (++s == STAGES) s = 0;
        }
    } else {
        // ---------------- CONSUMER (4 warps per stream) ----------------
        int st   = wid >> 2;                  // stream 0/1
        int ncol = (wid & 3) * 32;            // warp's 32 N-columns
        int barF = 1 + st * 6, barE = 4 + st * 6;
        int g = lane >> 2, tid4 = lane & 3;
        uint32_t lrow = (uint32_t)(lane & 15);
        uint32_t lcol = (uint32_t)((lane >> 4) << 3);
        // B ldmatrix.x4 over 16-n-row pair
        uint32_t bn = (uint32_t)(((lane >> 4) << 3) + (lane & 7));
        uint32_t bk = (uint32_t)(((lane >> 3) & 1) << 3);

        int i = 0, s = 0;
        for (int tile = blockIdx.x * 2 + st; tile < NT64; tile += GRID * 2, i++) {
            SBAR_SYNC(barF + s);                     // wait full[s]
            uint32_t xh = sb + SM_STAGE(st, s);

            float acc[4][4][4];
#pragma unroll
            for (int ii = 0; ii < 4; ii++)
#pragma unroll
                for (int j = 0; j < 4; j++)
#pragma unroll
                    for (int e = 0; e < 4; e++) acc[ii][j][e] = 0.0f;

#pragma unroll
            for (int ks = 0; ks < 8; ks++) {
                uint32_t Ah[4][4];
#pragma unroll
                for (int ii = 0; ii < 4; ii++) {
                    uint32_t off = (uint32_t)(ii * 16 + lrow) * PITCHB +
                                   (uint32_t)(ks * 16 + lcol) * 2;
                    LDSM4(Ah[ii], xh + off);
                }
                uint32_t Bh[4][2];
#pragma unroll
                for (int jp = 0; jp < 2; jp++) {
                    uint32_t boff = (uint32_t)(ncol + jp * 16 + bn) * PITCHB +
                                    (uint32_t)(ks * 16 + bk) * 2;
                    uint32_t Bq[4];
                    LDSM4(Bq, sbW + boff);
                    Bh[jp * 2 + 0][0] = Bq[0]; Bh[jp * 2 + 0][1] = Bq[1];
                    Bh[jp * 2 + 1][0] = Bq[2]; Bh[jp * 2 + 1][1] = Bq[3];
                }
#pragma unroll
                for (int ii = 0; ii < 4; ii++)
#pragma unroll
                    for (int j = 0; j < 4; j++) MMA16816(acc[ii][j], Ah[ii], Bh[j]);
            }
            SBAR_ARRIVE(barE + s);                   // empty[s] (reads done)

            float* yt = y + (size_t)tile * 64 * DIM;
#pragma unroll
            for (int ii = 0; ii < 4; ii++) {
                int row0 = ii * 16 + g;
#pragma unroll
                for (int j = 0; j < 4; j++) {
                    int cb = ncol + j * 8 + tid4 * 2;
                    float2 v0, v1;
                    v0.x = acc[ii][j][0]; v0.y = acc[ii][j][1];
                    v1.x = acc[ii][j][2]; v1.y = acc[ii][j][3];
                    __stcs((float2*)(yt + (size_t)row0 * DIM + cb), v0);
                    __stcs((float2*)(yt + (size_t)(row0 + 8) * DIM + cb), v1);
                }
            }
            if (++s == STAGES) s = 0;
        }
    }
}

// ---------------------------------------------------------------------------
// Launch
// ---------------------------------------------------------------------------
extern "C" void kernel_launch(void* const* d_in, const int* in_sizes, int n_in,
                              void* d_out, int out_size) {
    const float* x    = (const float*)d_in[0];   // [BATCH, DIM]
    const float* V    = (const float*)d_in[1];   // [DIM, DIM] (v_i = columns)
    const float* sc   = (const float*)d_in[2];   // [1]
    const float* diag = (const float*)d_in[3];   // [DIM]
    float* out = (float*)d_out;

    cudaFuncSetAttribute(fused_kernel,
                         cudaFuncAttributeMaxDynamicSharedMemorySize, SMEM_BYTES);
    fused_kernel<<<GRID, 384, SMEM_BYTES>>>(x, V, sc, diag, out, out_size);
}